// round 8
// baseline (speedup 1.0000x reference)
#include <cuda_runtime.h>

// LSTMNet: 3-layer LSTM (H=6, input=1), B=8192, T=512, FC head on final h2.
// Round 8: f32x2 packed ACROSS ELEMENTS. Each lane-k handles hidden unit k of
// TWO batch elements; gate accumulators are (gate_e0, gate_e1) pairs, so the
// (v,v) pack2 duplication tax of R5 vanishes. 10 elements/warp, 820 warps,
// 137 blocks x 6 warps = single wave. Weights pre-duplicated (w,w) in smem.

#define HD 6
#define TT 512
#define PK 292     // floats per lane-k slice; 1168B stride == 16 mod 128 -> conflict-free
#define WPB 6
#define TPB (WPB * 32)
#define EPW 10     // elements per warp
__device__ float g_packk[6 * PK];

// per-k slice layout (floats; ALL values prescaled: sigmoid rows * -log2e,
// tanh row * -2log2e; every weight/bias duplicated as (w,w) pairs):
//   0: b0 dup (8)        8: wx0 dup (8)       16+8j: Whh0 col j dup (j=0..5)
//  64: b1 dup (8)       72+8j: Wih1 col j    120+8j: Whh1 col j
// 168: b2 dup (8)      176+8j: Wih2 col j    224+8j: Whh2 col j
// 288: fc_w[k]  289: fc_b

__global__ void prep_kernel(
    const float* __restrict__ Wih0, const float* __restrict__ Whh0,
    const float* __restrict__ bih0, const float* __restrict__ bhh0,
    const float* __restrict__ Wih1, const float* __restrict__ Whh1,
    const float* __restrict__ bih1, const float* __restrict__ bhh1,
    const float* __restrict__ Wih2, const float* __restrict__ Whh2,
    const float* __restrict__ bih2, const float* __restrict__ bhh2,
    const float* __restrict__ fcw, const float* __restrict__ fcb)
{
    int tid = threadIdx.x;
    if (tid < 24) {
        int k = tid / 4, g = tid % 4;
        float s = (g == 2) ? -2.88539008177793f : -1.44269504088896f;
        int row = g * HD + k;             // PyTorch gate order i,f,g,o
        float* p = g_packk + k * PK;
        float v;
        v = (bih0[row] + bhh0[row]) * s;  p[0 + 2*g] = v;   p[1 + 2*g] = v;
        v = Wih0[row] * s;                p[8 + 2*g] = v;   p[9 + 2*g] = v;
        v = (bih1[row] + bhh1[row]) * s;  p[64 + 2*g] = v;  p[65 + 2*g] = v;
        v = (bih2[row] + bhh2[row]) * s;  p[168 + 2*g] = v; p[169 + 2*g] = v;
        for (int j = 0; j < HD; j++) {
            v = Whh0[row * HD + j] * s;  p[16  + 8*j + 2*g] = v; p[17  + 8*j + 2*g] = v;
            v = Wih1[row * HD + j] * s;  p[72  + 8*j + 2*g] = v; p[73  + 8*j + 2*g] = v;
            v = Whh1[row * HD + j] * s;  p[120 + 8*j + 2*g] = v; p[121 + 8*j + 2*g] = v;
            v = Wih2[row * HD + j] * s;  p[176 + 8*j + 2*g] = v; p[177 + 8*j + 2*g] = v;
            v = Whh2[row * HD + j] * s;  p[224 + 8*j + 2*g] = v; p[225 + 8*j + 2*g] = v;
        }
    }
    if (tid < 6) {
        g_packk[tid * PK + 288] = fcw[tid];
        g_packk[tid * PK + 289] = fcb[0];
    }
}

typedef unsigned long long ull;

// ---- f32x2 + fast-math primitives ----
__device__ __forceinline__ void fma2(ull& d, ull a, ull b, ull c) {
    asm("fma.rn.f32x2 %0, %1, %2, %3;" : "=l"(d) : "l"(a), "l"(b), "l"(c));
}
__device__ __forceinline__ void mul2(ull& d, ull a, ull b) {
    asm("mul.rn.f32x2 %0, %1, %2;" : "=l"(d) : "l"(a), "l"(b));
}
__device__ __forceinline__ void add2(ull& d, ull a, ull b) {
    asm("add.rn.f32x2 %0, %1, %2;" : "=l"(d) : "l"(a), "l"(b));
}
__device__ __forceinline__ ull pack2(float x, float y) {
    ull d; asm("mov.b64 %0, {%1, %2};" : "=l"(d) : "f"(x), "f"(y)); return d;
}
__device__ __forceinline__ void unpack2(float& x, float& y, ull v) {
    asm("mov.b64 {%0, %1}, %2;" : "=f"(x), "=f"(y) : "l"(v));
}
__device__ __forceinline__ float ex2_ap(float x) {
    float y; asm("ex2.approx.f32 %0, %1;" : "=f"(y) : "f"(x)); return y;
}
__device__ __forceinline__ float rcp_ap(float x) {
    float y; asm("rcp.approx.f32 %0, %1;" : "=f"(y) : "f"(x)); return y;
}

// one element's cell from prescaled gate pre-activations (paired-rcp trick)
__device__ __forceinline__ void cell_s(float ai, float af, float ag, float ao,
                                       float& c, float& h)
{
    float ei = ex2_ap(ai), ef = ex2_ap(af), eg = ex2_ap(ag), eo = ex2_ap(ao);
    float a1 = 1.f + ei, a2 = 1.f + ef, a3 = 1.f + eg, a4 = 1.f + eo;
    float r1 = rcp_ap(a1 * a2);
    float r2 = rcp_ap(a3 * a4);
    float si = r1 * a2;
    float sf = r1 * a1;
    float so = r2 * a3;
    float tg = fmaf(r2 * a4, 2.f, -1.f);
    c = fmaf(sf, c, si * tg);
    float ec = ex2_ap(c * -2.88539008177793f);
    float th = fmaf(rcp_ap(1.f + ec), 2.f, -1.f);
    h = so * th;
}

// unpack 4 gate-pairs (packed across elements), run both cells, broadcast+pack
#define CELL_BCAST(AI, AF, AG, AO, CA, CB, HA, HB, HP)                 \
    {   float ia_, ib_, fa_, fb_, ga_, gb_, oa_, ob_;                  \
        unpack2(ia_, ib_, AI); unpack2(fa_, fb_, AF);                  \
        unpack2(ga_, gb_, AG); unpack2(oa_, ob_, AO);                  \
        cell_s(ia_, fa_, ga_, oa_, CA, HA);                            \
        cell_s(ib_, fb_, gb_, ob_, CB, HB);                            \
        _Pragma("unroll")                                              \
        for (int j = 0; j < HD; j++) {                                 \
            float va_ = __shfl_sync(0xffffffffu, HA, sb + j);          \
            float vb_ = __shfl_sync(0xffffffffu, HB, sb + j);          \
            (HP)[j] = pack2(va_, vb_);                                 \
        }                                                              \
    }

__global__ void __launch_bounds__(TPB, 1)
lstm2x_kernel(const float* __restrict__ x, float* __restrict__ out, int B)
{
    __shared__ __align__(16) float sw[6 * PK];
    for (int i = threadIdx.x; i < 6 * PK; i += TPB) sw[i] = g_packk[i];
    __syncthreads();

    int wid  = blockIdx.x * WPB + (threadIdx.x >> 5);
    int lane = threadIdx.x & 31;
    if (wid * EPW >= B) return;                     // warp-uniform exit

    int sub = lane / HD;                            // 0..4 active, 5 = spare
    int k   = lane - sub * HD;
    int sb  = (sub < 5) ? sub * HD : 0;             // shuffle base
    int subv = (sub < 5) ? sub : 0;

    int ea = wid * EPW + 2 * subv;                  // element A
    int eb = ea + 1;                                // element B
    bool oka = (sub < 5) && (ea < B) && (k == 0);
    bool okb = (sub < 5) && (eb < B) && (k == 0);
    int la = (ea < B) ? ea : (B - 1);               // clamped for loads
    int lb = (eb < B) ? eb : (B - 1);

    const float* pk = sw + k * PK;
    const ull* s8 = reinterpret_cast<const ull*>(pk);

    // hoist: biases, layer-0 weights (reg budget 341/thread at 192 thr/blk)
    ull b0i = s8[0],  b0f = s8[1],  b0g = s8[2],  b0o = s8[3];
    ull wxi = s8[4],  wxf = s8[5],  wxg = s8[6],  wxo = s8[7];
    ull w0r[24];
#pragma unroll
    for (int i = 0; i < 24; i++) w0r[i] = s8[8 + i];   // w0r[4j+g]
    ull b1i = s8[32], b1f = s8[33], b1g = s8[34], b1o = s8[35];
    ull b2i = s8[84], b2f = s8[85], b2g = s8[86], b2o = s8[87];
    float fcwk = pk[288], fcbv = pk[289];

    const ulonglong2* w1in  = reinterpret_cast<const ulonglong2*>(s8 + 36);  // col j: [2j],[2j+1]
    const ulonglong2* w1rec = reinterpret_cast<const ulonglong2*>(s8 + 60);
    const ulonglong2* w2in  = reinterpret_cast<const ulonglong2*>(s8 + 88);
    const ulonglong2* w2rec = reinterpret_cast<const ulonglong2*>(s8 + 112);

    const float4* xpa = reinterpret_cast<const float4*>(x + (size_t)la * TT);
    const float4* xpb = reinterpret_cast<const float4*>(x + (size_t)lb * TT);

    // state: broadcast vectors packed (vA, vB); cells scalar per element
    ull h0p[HD], h1p[HD], h2p[HD];
    float c0a = 0.f, c0b = 0.f, c1a = 0.f, c1b = 0.f, c2a = 0.f, c2b = 0.f;
    float h2a = 0.f, h2b = 0.f;
    ull z = pack2(0.f, 0.f);
#pragma unroll
    for (int j = 0; j < HD; j++) { h0p[j] = z; h1p[j] = z; h2p[j] = z; }

#pragma unroll 1
    for (int t4 = 0; t4 < TT / 4; t4++) {
        float4 xqa = __ldg(xpa + t4);
        float4 xqb = __ldg(xpb + t4);
#pragma unroll
        for (int u = 0; u < 4; u++) {
            float xta = (u == 0) ? xqa.x : (u == 1) ? xqa.y : (u == 2) ? xqa.z : xqa.w;
            float xtb = (u == 0) ? xqb.x : (u == 1) ? xqb.y : (u == 2) ? xqb.z : xqb.w;
            ull xx = pack2(xta, xtb);

            // ---- layer 0: b0 + wx*x + Whh0 @ h0p (2 chains) ----
            {
                ull ai, af, ag, ao, qi, qf, qg, qo;
                fma2(ai, wxi, xx, b0i);
                fma2(af, wxf, xx, b0f);
                fma2(ag, wxg, xx, b0g);
                fma2(ao, wxo, xx, b0o);
#pragma unroll
                for (int j = 0; j < 3; j++) {
                    fma2(ai, w0r[4*j+0], h0p[j], ai);
                    fma2(af, w0r[4*j+1], h0p[j], af);
                    fma2(ag, w0r[4*j+2], h0p[j], ag);
                    fma2(ao, w0r[4*j+3], h0p[j], ao);
                }
                mul2(qi, w0r[12], h0p[3]);
                mul2(qf, w0r[13], h0p[3]);
                mul2(qg, w0r[14], h0p[3]);
                mul2(qo, w0r[15], h0p[3]);
#pragma unroll
                for (int j = 4; j < HD; j++) {
                    fma2(qi, w0r[4*j+0], h0p[j], qi);
                    fma2(qf, w0r[4*j+1], h0p[j], qf);
                    fma2(qg, w0r[4*j+2], h0p[j], qg);
                    fma2(qo, w0r[4*j+3], h0p[j], qo);
                }
                add2(ai, ai, qi); add2(af, af, qf);
                add2(ag, ag, qg); add2(ao, ao, qo);
                float h0na, h0nb;
                CELL_BCAST(ai, af, ag, ao, c0a, c0b, h0na, h0nb, h0p);
            }

            // ---- layer 1: b1 + Wih1 @ h0p + Whh1 @ h1p (2 chains) ----
            {
                ull ai, af, ag, ao, qi, qf, qg, qo;
                {   ulonglong2 wa = w1in[0], wb = w1in[1];
                    fma2(ai, wa.x, h0p[0], b1i);
                    fma2(af, wa.y, h0p[0], b1f);
                    fma2(ag, wb.x, h0p[0], b1g);
                    fma2(ao, wb.y, h0p[0], b1o); }
#pragma unroll
                for (int j = 1; j < HD; j++) {
                    ulonglong2 wa = w1in[2*j], wb = w1in[2*j+1];
                    fma2(ai, wa.x, h0p[j], ai);
                    fma2(af, wa.y, h0p[j], af);
                    fma2(ag, wb.x, h0p[j], ag);
                    fma2(ao, wb.y, h0p[j], ao);
                }
                {   ulonglong2 wa = w1rec[0], wb = w1rec[1];
                    mul2(qi, wa.x, h1p[0]);
                    mul2(qf, wa.y, h1p[0]);
                    mul2(qg, wb.x, h1p[0]);
                    mul2(qo, wb.y, h1p[0]); }
#pragma unroll
                for (int j = 1; j < HD; j++) {
                    ulonglong2 wa = w1rec[2*j], wb = w1rec[2*j+1];
                    fma2(qi, wa.x, h1p[j], qi);
                    fma2(qf, wa.y, h1p[j], qf);
                    fma2(qg, wb.x, h1p[j], qg);
                    fma2(qo, wb.y, h1p[j], qo);
                }
                add2(ai, ai, qi); add2(af, af, qf);
                add2(ag, ag, qg); add2(ao, ao, qo);
                float h1na, h1nb;
                CELL_BCAST(ai, af, ag, ao, c1a, c1b, h1na, h1nb, h1p);
            }

            // ---- layer 2: b2 + Wih2 @ h1p + Whh2 @ h2p (2 chains) ----
            {
                ull ai, af, ag, ao, qi, qf, qg, qo;
                {   ulonglong2 wa = w2in[0], wb = w2in[1];
                    fma2(ai, wa.x, h1p[0], b2i);
                    fma2(af, wa.y, h1p[0], b2f);
                    fma2(ag, wb.x, h1p[0], b2g);
                    fma2(ao, wb.y, h1p[0], b2o); }
#pragma unroll
                for (int j = 1; j < HD; j++) {
                    ulonglong2 wa = w2in[2*j], wb = w2in[2*j+1];
                    fma2(ai, wa.x, h1p[j], ai);
                    fma2(af, wa.y, h1p[j], af);
                    fma2(ag, wb.x, h1p[j], ag);
                    fma2(ao, wb.y, h1p[j], ao);
                }
                {   ulonglong2 wa = w2rec[0], wb = w2rec[1];
                    mul2(qi, wa.x, h2p[0]);
                    mul2(qf, wa.y, h2p[0]);
                    mul2(qg, wb.x, h2p[0]);
                    mul2(qo, wb.y, h2p[0]); }
#pragma unroll
                for (int j = 1; j < HD; j++) {
                    ulonglong2 wa = w2rec[2*j], wb = w2rec[2*j+1];
                    fma2(qi, wa.x, h2p[j], qi);
                    fma2(qf, wa.y, h2p[j], qf);
                    fma2(qg, wb.x, h2p[j], qg);
                    fma2(qo, wb.y, h2p[j], qo);
                }
                add2(ai, ai, qi); add2(af, af, qf);
                add2(ag, ag, qg); add2(ao, ao, qo);
                CELL_BCAST(ai, af, ag, ao, c2a, c2b, h2a, h2b, h2p);
            }
        }
    }

    // FC head per element: out[e] = sum_k h2[k]*fc_w[k] + fc_b
    float ra = h2a * fcwk;
    float rb = h2b * fcwk;
    float sa = fcbv, sbv = fcbv;
#pragma unroll
    for (int j = 0; j < HD; j++) {
        sa  += __shfl_sync(0xffffffffu, ra, sb + j);
        sbv += __shfl_sync(0xffffffffu, rb, sb + j);
    }
    if (oka) out[ea] = sa;
    if (okb) out[eb] = sbv;
}

extern "C" void kernel_launch(void* const* d_in, const int* in_sizes, int n_in,
                              void* d_out, int out_size)
{
    const float* x = (const float*)d_in[0];
    int B = in_sizes[0] / TT;                  // 8192
    int warps  = (B + EPW - 1) / EPW;          // 820
    int blocks = (warps + WPB - 1) / WPB;      // 137

    prep_kernel<<<1, 64>>>(
        (const float*)d_in[1],  (const float*)d_in[2],
        (const float*)d_in[3],  (const float*)d_in[4],
        (const float*)d_in[5],  (const float*)d_in[6],
        (const float*)d_in[7],  (const float*)d_in[8],
        (const float*)d_in[9],  (const float*)d_in[10],
        (const float*)d_in[11], (const float*)d_in[12],
        (const float*)d_in[13], (const float*)d_in[14]);

    lstm2x_kernel<<<blocks, TPB>>>(x, (float*)d_out, B);
}